// round 4
// baseline (speedup 1.0000x reference)
#include <cuda_runtime.h>
#include <cstdint>

#define SEQ    4096
#define DIM    1024
#define HEADS  16
#define DHEAD  64
#define QBETA  0.125f   // 1/sqrt(64)

// Scratch (allocation-free rule: __device__ globals)
__device__ float g_q[SEQ * DIM];
__device__ float g_k[SEQ * DIM];
__device__ float g_v[SEQ * DIM];
__device__ float g_att[SEQ * DIM];

// ---------------------------------------------------------------------------
// tf32 helpers
// ---------------------------------------------------------------------------
__device__ __forceinline__ unsigned f2tf(float x) {
    unsigned u;
    asm("cvt.rna.tf32.f32 %0, %1;" : "=r"(u) : "f"(x));
    return u;
}

__device__ __forceinline__ void mma_tf32(float* c,
                                         unsigned a0, unsigned a1, unsigned a2, unsigned a3,
                                         unsigned b0, unsigned b1) {
    asm volatile(
        "mma.sync.aligned.m16n8k8.row.col.f32.tf32.tf32.f32 "
        "{%0,%1,%2,%3},{%4,%5,%6,%7},{%8,%9},{%0,%1,%2,%3};"
        : "+f"(c[0]), "+f"(c[1]), "+f"(c[2]), "+f"(c[3])
        : "r"(a0), "r"(a1), "r"(a2), "r"(a3), "r"(b0), "r"(b1));
}

// ---------------------------------------------------------------------------
// tf32 GEMM: C[4096,1024] = alpha * A[4096,1024] @ B[1024,1024] (+bias)
// Block tile 128x128, K-step 32, 256 threads = 8 warps (4x2), warp tile 32x64
// (mi=2, ni=8) -> LDS-instr/mma = 1.5.
// Conflict-free scalar gathers: A ld=36 (bank 4g+t..), B ld=136 (bank 8t+g).
// ---------------------------------------------------------------------------
#define GA_LD 36
#define GB_LD 136

__device__ __forceinline__ void gemm_tf32_tile(
    const float* __restrict__ A, const float* __restrict__ B,
    float* __restrict__ C, float alpha, const float* __restrict__ bias)
{
    __shared__ unsigned As[128 * GA_LD];
    __shared__ unsigned Bs[32 * GB_LD];

    const int tid  = threadIdx.x;
    const int lane = tid & 31;
    const int warp = tid >> 5;
    const int g = lane >> 2;   // fragment row
    const int t = lane & 3;    // fragment col
    const int wm = warp & 3;   // warp row (x32)
    const int wn = warp >> 2;  // warp col (x64)
    const int row0 = blockIdx.y * 128;
    const int col0 = blockIdx.x * 128;

    float acc[2][8][4];
#pragma unroll
    for (int mi = 0; mi < 2; mi++)
#pragma unroll
        for (int ni = 0; ni < 8; ni++)
#pragma unroll
            for (int e = 0; e < 4; e++) acc[mi][ni][e] = 0.f;

    for (int k0 = 0; k0 < DIM; k0 += 32) {
        // stage A 128x32 (tf32 bits)
#pragma unroll
        for (int p = 0; p < 4; p++) {
            const int r = (tid >> 3) + p * 32;
            const int c = (tid & 7) * 4;
            float4 v = *(const float4*)&A[(size_t)(row0 + r) * DIM + k0 + c];
            unsigned* d = &As[r * GA_LD + c];
            d[0] = f2tf(v.x); d[1] = f2tf(v.y); d[2] = f2tf(v.z); d[3] = f2tf(v.w);
        }
        // stage B 32x128
#pragma unroll
        for (int p = 0; p < 4; p++) {
            const int r = (tid >> 5) + p * 8;
            const int c = (tid & 31) * 4;
            float4 v = *(const float4*)&B[(size_t)(k0 + r) * DIM + col0 + c];
            unsigned* d = &Bs[r * GB_LD + c];
            d[0] = f2tf(v.x); d[1] = f2tf(v.y); d[2] = f2tf(v.z); d[3] = f2tf(v.w);
        }
        __syncthreads();

#pragma unroll
        for (int kk = 0; kk < 4; kk++) {
            unsigned a[2][4];
#pragma unroll
            for (int mi = 0; mi < 2; mi++) {
                const int rbm = wm * 32 + mi * 16;
                a[mi][0] = As[(rbm + g)     * GA_LD + kk * 8 + t];
                a[mi][1] = As[(rbm + g + 8) * GA_LD + kk * 8 + t];
                a[mi][2] = As[(rbm + g)     * GA_LD + kk * 8 + t + 4];
                a[mi][3] = As[(rbm + g + 8) * GA_LD + kk * 8 + t + 4];
            }
#pragma unroll
            for (int ni = 0; ni < 8; ni++) {
                const unsigned b0 = Bs[(kk * 8 + t)     * GB_LD + wn * 64 + ni * 8 + g];
                const unsigned b1 = Bs[(kk * 8 + t + 4) * GB_LD + wn * 64 + ni * 8 + g];
                mma_tf32(acc[0][ni], a[0][0], a[0][1], a[0][2], a[0][3], b0, b1);
                mma_tf32(acc[1][ni], a[1][0], a[1][1], a[1][2], a[1][3], b0, b1);
            }
        }
        __syncthreads();
    }

    // epilogue
#pragma unroll
    for (int mi = 0; mi < 2; mi++) {
        const int rb = row0 + wm * 32 + mi * 16;
#pragma unroll
        for (int ni = 0; ni < 8; ni++) {
            const int cb = col0 + wn * 64 + ni * 8 + 2 * t;
            float bv0 = 0.f, bv1 = 0.f;
            if (bias) { bv0 = bias[cb]; bv1 = bias[cb + 1]; }
            float2 o0 = { acc[mi][ni][0] * alpha + bv0, acc[mi][ni][1] * alpha + bv1 };
            float2 o1 = { acc[mi][ni][2] * alpha + bv0, acc[mi][ni][3] * alpha + bv1 };
            *(float2*)&C[(size_t)(rb + g)     * DIM + cb] = o0;
            *(float2*)&C[(size_t)(rb + g + 8) * DIM + cb] = o1;
        }
    }
}

__global__ void __launch_bounds__(256) qkv_kernel(
    const float* __restrict__ x,
    const float* __restrict__ Wq,
    const float* __restrict__ Wk,
    const float* __restrict__ Wv)
{
    if (blockIdx.z == 0)      gemm_tf32_tile(x, Wq, g_q, QBETA, nullptr);
    else if (blockIdx.z == 1) gemm_tf32_tile(x, Wk, g_k, 1.f, nullptr);
    else                      gemm_tf32_tile(x, Wv, g_v, 1.f, nullptr);
}

__global__ void __launch_bounds__(256) out_kernel(
    const float* __restrict__ Wo,
    const float* __restrict__ bo,
    float* __restrict__ out)
{
    gemm_tf32_tile(g_att, Wo, out, 1.f, bo);
}

// ---------------------------------------------------------------------------
// Flash attention, causal, tf32 mma. One block = (64 q-rows, one head),
// 128 threads = 4 warps, each warp owns 16 q-rows.
// Q fragments hoisted to registers (jt-invariant); Q smem buffer reused for P
// (both warp-private). smem = K[64][68] + V[64][72] + QP[64][68] = 53.2KB
// -> 3 blocks/SM.
// ---------------------------------------------------------------------------
#define FL_KLD 68
#define FL_VLD 72
#define FL_PLD 68
#define OFF_K 0
#define OFF_V (OFF_K + 64 * FL_KLD)
#define OFF_P (OFF_V + 64 * FL_VLD)
#define FL_SMEM_UINTS (OFF_P + 64 * FL_PLD)
#define FL_SMEM_BYTES (FL_SMEM_UINTS * 4)

__global__ void __launch_bounds__(128, 3) flash_kernel()
{
    extern __shared__ unsigned sm[];
    unsigned* Ks = sm + OFF_K;
    unsigned* Vs = sm + OFF_V;
    unsigned* Ps = sm + OFF_P;   // doubles as Q staging buffer

    const int tid  = threadIdx.x;
    const int lane = tid & 31;
    const int warp = tid >> 5;
    const int g = lane >> 2;
    const int t = lane & 3;
    const int h  = blockIdx.y;
    const int qt = gridDim.x - 1 - blockIdx.x;   // heaviest q-tiles first
    const int hoff = h * DHEAD;
    const int rb = warp * 16;                    // warp's local row base

    // stage Q (warp-local rows: thread tid>>1 covers rows 16w..16w+15)
    {
        const int r = tid >> 1, cb = (tid & 1) * 32;
        const float4* src = (const float4*)&g_q[(size_t)(qt * 64 + r) * DIM + hoff + cb];
#pragma unroll
        for (int i = 0; i < 8; i++) {
            float4 v = src[i];
            unsigned* d = &Ps[r * FL_PLD + cb + i * 4];
            d[0] = f2tf(v.x); d[1] = f2tf(v.y); d[2] = f2tf(v.z); d[3] = f2tf(v.w);
        }
    }
    __syncwarp();

    // hoist Q fragments to registers (loop-invariant)
    unsigned qa[8][4];
#pragma unroll
    for (int kk = 0; kk < 8; kk++) {
        qa[kk][0] = Ps[(rb + g)     * FL_PLD + kk * 8 + t];
        qa[kk][1] = Ps[(rb + g + 8) * FL_PLD + kk * 8 + t];
        qa[kk][2] = Ps[(rb + g)     * FL_PLD + kk * 8 + t + 4];
        qa[kk][3] = Ps[(rb + g + 8) * FL_PLD + kk * 8 + t + 4];
    }
    __syncwarp();   // Ps now free for P reuse (warp-private region)

    float o[8][4];
#pragma unroll
    for (int ni = 0; ni < 8; ni++)
#pragma unroll
        for (int e = 0; e < 4; e++) o[ni][e] = 0.f;
    float m0 = -1e30f, m1 = -1e30f, l0 = 0.f, l1 = 0.f;

    for (int jt = 0; jt <= qt; jt++) {
        // stage K and V tiles (block-wide)
        {
            const int r = tid >> 1, cb = (tid & 1) * 32;
            const float4* ks = (const float4*)&g_k[(size_t)(jt * 64 + r) * DIM + hoff + cb];
            const float4* vs = (const float4*)&g_v[(size_t)(jt * 64 + r) * DIM + hoff + cb];
#pragma unroll
            for (int i = 0; i < 8; i++) {
                float4 v = ks[i];
                unsigned* d = &Ks[r * FL_KLD + cb + i * 4];
                d[0] = f2tf(v.x); d[1] = f2tf(v.y); d[2] = f2tf(v.z); d[3] = f2tf(v.w);
                float4 w = vs[i];
                unsigned* e = &Vs[r * FL_VLD + cb + i * 4];
                e[0] = f2tf(w.x); e[1] = f2tf(w.y); e[2] = f2tf(w.z); e[3] = f2tf(w.w);
            }
        }
        __syncthreads();

        // S = Q @ K^T   (m16 x n64, k=64)
        float s[8][4];
#pragma unroll
        for (int ni = 0; ni < 8; ni++)
#pragma unroll
            for (int e = 0; e < 4; e++) s[ni][e] = 0.f;

#pragma unroll
        for (int kk = 0; kk < 8; kk++) {
#pragma unroll
            for (int ni = 0; ni < 8; ni++) {
                const unsigned b0 = Ks[(ni * 8 + g) * FL_KLD + kk * 8 + t];
                const unsigned b1 = Ks[(ni * 8 + g) * FL_KLD + kk * 8 + t + 4];
                mma_tf32(s[ni], qa[kk][0], qa[kk][1], qa[kk][2], qa[kk][3], b0, b1);
            }
        }

        // causal mask (diagonal tile only)
        if (jt == qt) {
            const int li0 = rb + g, li1 = li0 + 8;
#pragma unroll
            for (int ni = 0; ni < 8; ni++) {
                const int j0 = ni * 8 + 2 * t, j1 = j0 + 1;
                if (j0 > li0) s[ni][0] = -1e30f;
                if (j1 > li0) s[ni][1] = -1e30f;
                if (j0 > li1) s[ni][2] = -1e30f;
                if (j1 > li1) s[ni][3] = -1e30f;
            }
        }

        // online softmax (rows g and g+8; 4 lanes per row -> shfl_xor 1,2)
        float rm0 = -1e30f, rm1 = -1e30f;
#pragma unroll
        for (int ni = 0; ni < 8; ni++) {
            rm0 = fmaxf(rm0, fmaxf(s[ni][0], s[ni][1]));
            rm1 = fmaxf(rm1, fmaxf(s[ni][2], s[ni][3]));
        }
        rm0 = fmaxf(rm0, __shfl_xor_sync(0xffffffffu, rm0, 1));
        rm0 = fmaxf(rm0, __shfl_xor_sync(0xffffffffu, rm0, 2));
        rm1 = fmaxf(rm1, __shfl_xor_sync(0xffffffffu, rm1, 1));
        rm1 = fmaxf(rm1, __shfl_xor_sync(0xffffffffu, rm1, 2));

        const float mn0 = fmaxf(m0, rm0), mn1 = fmaxf(m1, rm1);
        const float corr0 = __expf(m0 - mn0), corr1 = __expf(m1 - mn1);
        m0 = mn0; m1 = mn1;

        float rs0 = 0.f, rs1 = 0.f;
#pragma unroll
        for (int ni = 0; ni < 8; ni++) {
            s[ni][0] = __expf(s[ni][0] - mn0);
            s[ni][1] = __expf(s[ni][1] - mn0);
            s[ni][2] = __expf(s[ni][2] - mn1);
            s[ni][3] = __expf(s[ni][3] - mn1);
            rs0 += s[ni][0] + s[ni][1];
            rs1 += s[ni][2] + s[ni][3];
            Ps[(rb + g)     * FL_PLD + ni * 8 + 2 * t]     = f2tf(s[ni][0]);
            Ps[(rb + g)     * FL_PLD + ni * 8 + 2 * t + 1] = f2tf(s[ni][1]);
            Ps[(rb + g + 8) * FL_PLD + ni * 8 + 2 * t]     = f2tf(s[ni][2]);
            Ps[(rb + g + 8) * FL_PLD + ni * 8 + 2 * t + 1] = f2tf(s[ni][3]);
        }
        rs0 += __shfl_xor_sync(0xffffffffu, rs0, 1);
        rs0 += __shfl_xor_sync(0xffffffffu, rs0, 2);
        rs1 += __shfl_xor_sync(0xffffffffu, rs1, 1);
        rs1 += __shfl_xor_sync(0xffffffffu, rs1, 2);
        l0 = l0 * corr0 + rs0;
        l1 = l1 * corr1 + rs1;

#pragma unroll
        for (int ni = 0; ni < 8; ni++) {
            o[ni][0] *= corr0; o[ni][1] *= corr0;
            o[ni][2] *= corr1; o[ni][3] *= corr1;
        }
        __syncwarp();   // Ps write -> read is warp-local

        // O += P @ V   (m16 x n64, k=64)
#pragma unroll
        for (int kk = 0; kk < 8; kk++) {
            const unsigned a0 = Ps[(rb + g)     * FL_PLD + kk * 8 + t];
            const unsigned a1 = Ps[(rb + g + 8) * FL_PLD + kk * 8 + t];
            const unsigned a2 = Ps[(rb + g)     * FL_PLD + kk * 8 + t + 4];
            const unsigned a3 = Ps[(rb + g + 8) * FL_PLD + kk * 8 + t + 4];
#pragma unroll
            for (int ni = 0; ni < 8; ni++) {
                const unsigned b0 = Vs[(kk * 8 + t)     * FL_VLD + ni * 8 + g];
                const unsigned b1 = Vs[(kk * 8 + t + 4) * FL_VLD + ni * 8 + g];
                mma_tf32(o[ni], a0, a1, a2, a3, b0, b1);
            }
        }
        __syncthreads();   // protect K/V tiles before next stage
    }

    // normalize + write [n, h*d] layout
    const float inv0 = 1.f / l0, inv1 = 1.f / l1;
    const int row = qt * 64 + rb;
#pragma unroll
    for (int ni = 0; ni < 8; ni++) {
        const int cb = hoff + ni * 8 + 2 * t;
        float2 v0 = { o[ni][0] * inv0, o[ni][1] * inv0 };
        float2 v1 = { o[ni][2] * inv1, o[ni][3] * inv1 };
        *(float2*)&g_att[(size_t)(row + g)     * DIM + cb] = v0;
        *(float2*)&g_att[(size_t)(row + g + 8) * DIM + cb] = v1;
    }
}

// ---------------------------------------------------------------------------
extern "C" void kernel_launch(void* const* d_in, const int* in_sizes, int n_in,
                              void* d_out, int out_size)
{
    const float* x  = (const float*)d_in[0];
    const float* Wq = (const float*)d_in[1];
    const float* Wk = (const float*)d_in[2];
    const float* Wv = (const float*)d_in[3];
    const float* Wo = (const float*)d_in[4];
    const float* bo = (const float*)d_in[5];
    float* out = (float*)d_out;

    cudaFuncSetAttribute(flash_kernel,
                         cudaFuncAttributeMaxDynamicSharedMemorySize,
                         FL_SMEM_BYTES);

    qkv_kernel<<<dim3(DIM / 128, SEQ / 128, 3), 256>>>(x, Wq, Wk, Wv);
    flash_kernel<<<dim3(SEQ / 64, HEADS), 128, FL_SMEM_BYTES>>>();
    out_kernel<<<dim3(DIM / 128, SEQ / 128), 256>>>(Wo, bo, out);
}

// round 5
// speedup vs baseline: 1.4087x; 1.4087x over previous
#include <cuda_runtime.h>
#include <cstdint>

#define SEQ    4096
#define DIM    1024
#define HEADS  16
#define DHEAD  64
#define QBETA  0.125f   // 1/sqrt(64)

// Scratch (allocation-free rule: __device__ globals).
// Q/K/V/att are stored as tf32 BIT PATTERNS (unsigned) — the tf32 rounding
// happened at this point in the pipeline anyway, so numerics are identical.
__device__ unsigned g_q[SEQ * DIM];
__device__ unsigned g_k[SEQ * DIM];
__device__ unsigned g_v[SEQ * DIM];
__device__ unsigned g_att[SEQ * DIM];

// ---------------------------------------------------------------------------
// tf32 helpers
// ---------------------------------------------------------------------------
__device__ __forceinline__ unsigned f2tf(float x) {
    unsigned u;
    asm("cvt.rna.tf32.f32 %0, %1;" : "=r"(u) : "f"(x));
    return u;
}

__device__ __forceinline__ void mma_tf32(float* c,
                                         unsigned a0, unsigned a1, unsigned a2, unsigned a3,
                                         unsigned b0, unsigned b1) {
    asm volatile(
        "mma.sync.aligned.m16n8k8.row.col.f32.tf32.tf32.f32 "
        "{%0,%1,%2,%3},{%4,%5,%6,%7},{%8,%9},{%0,%1,%2,%3};"
        : "+f"(c[0]), "+f"(c[1]), "+f"(c[2]), "+f"(c[3])
        : "r"(a0), "r"(a1), "r"(a2), "r"(a3), "r"(b0), "r"(b1));
}

// ---------------------------------------------------------------------------
// tf32 GEMM (R3-proven shape): block tile 128x64, K-step 32, 256 threads =
// 8 warps (4x2), warp tile 32x32. A ld=36, B ld=72, conflict-free gathers.
// A_TF32: A already holds tf32 bits (skip cvt). OUT_TF32: store tf32 bits.
// ---------------------------------------------------------------------------
#define GA_LD 36
#define GB_LD 72

template<bool A_TF32, bool OUT_TF32>
__device__ __forceinline__ void gemm_tile(
    const void* __restrict__ Ap, const float* __restrict__ B,
    void* __restrict__ Cp, float alpha, const float* __restrict__ bias)
{
    __shared__ unsigned As[128 * GA_LD];
    __shared__ unsigned Bs[32 * GB_LD];

    const int tid  = threadIdx.x;
    const int lane = tid & 31;
    const int warp = tid >> 5;
    const int g = lane >> 2;
    const int t = lane & 3;
    const int wm = warp & 3;
    const int wn = warp >> 2;
    const int row0 = blockIdx.y * 128;
    const int col0 = blockIdx.x * 64;

    float acc[2][4][4];
#pragma unroll
    for (int mi = 0; mi < 2; mi++)
#pragma unroll
        for (int ni = 0; ni < 4; ni++)
#pragma unroll
            for (int e = 0; e < 4; e++) acc[mi][ni][e] = 0.f;

    for (int k0 = 0; k0 < DIM; k0 += 32) {
        // stage A 128x32
#pragma unroll
        for (int p = 0; p < 4; p++) {
            const int r = (tid >> 3) + p * 32;
            const int c = (tid & 7) * 4;
            if (A_TF32) {
                const unsigned* A32 = (const unsigned*)Ap;
                uint4 v = *(const uint4*)&A32[(size_t)(row0 + r) * DIM + k0 + c];
                *(uint4*)&As[r * GA_LD + c] = v;
            } else {
                const float* Af = (const float*)Ap;
                float4 v = *(const float4*)&Af[(size_t)(row0 + r) * DIM + k0 + c];
                unsigned* d = &As[r * GA_LD + c];
                d[0] = f2tf(v.x); d[1] = f2tf(v.y); d[2] = f2tf(v.z); d[3] = f2tf(v.w);
            }
        }
        // stage B 32x64 (always float input)
#pragma unroll
        for (int p = 0; p < 2; p++) {
            const int r = (tid >> 4) + p * 16;
            const int c = (tid & 15) * 4;
            float4 v = *(const float4*)&B[(size_t)(k0 + r) * DIM + col0 + c];
            unsigned* d = &Bs[r * GB_LD + c];
            d[0] = f2tf(v.x); d[1] = f2tf(v.y); d[2] = f2tf(v.z); d[3] = f2tf(v.w);
        }
        __syncthreads();

#pragma unroll
        for (int kk = 0; kk < 4; kk++) {
            unsigned a[2][4];
#pragma unroll
            for (int mi = 0; mi < 2; mi++) {
                const int rbm = wm * 32 + mi * 16;
                a[mi][0] = As[(rbm + g)     * GA_LD + kk * 8 + t];
                a[mi][1] = As[(rbm + g + 8) * GA_LD + kk * 8 + t];
                a[mi][2] = As[(rbm + g)     * GA_LD + kk * 8 + t + 4];
                a[mi][3] = As[(rbm + g + 8) * GA_LD + kk * 8 + t + 4];
            }
#pragma unroll
            for (int ni = 0; ni < 4; ni++) {
                const unsigned b0 = Bs[(kk * 8 + t)     * GB_LD + wn * 32 + ni * 8 + g];
                const unsigned b1 = Bs[(kk * 8 + t + 4) * GB_LD + wn * 32 + ni * 8 + g];
                mma_tf32(acc[0][ni], a[0][0], a[0][1], a[0][2], a[0][3], b0, b1);
                mma_tf32(acc[1][ni], a[1][0], a[1][1], a[1][2], a[1][3], b0, b1);
            }
        }
        __syncthreads();
    }

    // epilogue
#pragma unroll
    for (int mi = 0; mi < 2; mi++) {
        const int rb = row0 + wm * 32 + mi * 16;
#pragma unroll
        for (int ni = 0; ni < 4; ni++) {
            const int cb = col0 + wn * 32 + ni * 8 + 2 * t;
            float bv0 = 0.f, bv1 = 0.f;
            if (bias) { bv0 = bias[cb]; bv1 = bias[cb + 1]; }
            float v00 = acc[mi][ni][0] * alpha + bv0;
            float v01 = acc[mi][ni][1] * alpha + bv1;
            float v10 = acc[mi][ni][2] * alpha + bv0;
            float v11 = acc[mi][ni][3] * alpha + bv1;
            if (OUT_TF32) {
                unsigned* C32 = (unsigned*)Cp;
                uint2 o0 = { f2tf(v00), f2tf(v01) };
                uint2 o1 = { f2tf(v10), f2tf(v11) };
                *(uint2*)&C32[(size_t)(rb + g)     * DIM + cb] = o0;
                *(uint2*)&C32[(size_t)(rb + g + 8) * DIM + cb] = o1;
            } else {
                float* Cf = (float*)Cp;
                float2 o0 = { v00, v01 };
                float2 o1 = { v10, v11 };
                *(float2*)&Cf[(size_t)(rb + g)     * DIM + cb] = o0;
                *(float2*)&Cf[(size_t)(rb + g + 8) * DIM + cb] = o1;
            }
        }
    }
}

__global__ void __launch_bounds__(256) qkv_kernel(
    const float* __restrict__ x,
    const float* __restrict__ Wq,
    const float* __restrict__ Wk,
    const float* __restrict__ Wv)
{
    if (blockIdx.z == 0)      gemm_tile<false, true>(x, Wq, g_q, QBETA, nullptr);
    else if (blockIdx.z == 1) gemm_tile<false, true>(x, Wk, g_k, 1.f, nullptr);
    else                      gemm_tile<false, true>(x, Wv, g_v, 1.f, nullptr);
}

__global__ void __launch_bounds__(256) out_kernel(
    const float* __restrict__ Wo,
    const float* __restrict__ bo,
    float* __restrict__ out)
{
    gemm_tile<true, false>(g_att, Wo, out, 1.f, bo);
}

// ---------------------------------------------------------------------------
// Flash attention, causal, tf32 mma. One block = (64 q-rows, one head),
// 128 threads = 4 warps, each warp owns 16 q-rows.
// K/V/Q arrive as tf32 bits -> staging is pure uint4 copy (no cvt).
// Q fragments hoisted to registers; Q staging buffer aliased with P.
// smem = K[64][68] + V[64][72] + QP[64][68] = 53.2KB.
// ---------------------------------------------------------------------------
#define FL_KLD 68
#define FL_VLD 72
#define FL_PLD 68
#define OFF_K 0
#define OFF_V (OFF_K + 64 * FL_KLD)
#define OFF_P (OFF_V + 64 * FL_VLD)
#define FL_SMEM_UINTS (OFF_P + 64 * FL_PLD)
#define FL_SMEM_BYTES (FL_SMEM_UINTS * 4)

__global__ void __launch_bounds__(128) flash_kernel()
{
    extern __shared__ unsigned sm[];
    unsigned* Ks = sm + OFF_K;
    unsigned* Vs = sm + OFF_V;
    unsigned* Ps = sm + OFF_P;   // doubles as Q staging buffer

    const int tid  = threadIdx.x;
    const int lane = tid & 31;
    const int warp = tid >> 5;
    const int g = lane >> 2;
    const int t = lane & 3;
    const int h  = blockIdx.y;
    const int qt = gridDim.x - 1 - blockIdx.x;   // heaviest q-tiles first
    const int hoff = h * DHEAD;
    const int rb = warp * 16;

    // stage Q (bits; warp-local rows)
    {
        const int r = tid >> 1, cb = (tid & 1) * 32;
        const uint4* src = (const uint4*)&g_q[(size_t)(qt * 64 + r) * DIM + hoff + cb];
#pragma unroll
        for (int i = 0; i < 8; i++)
            *(uint4*)&Ps[r * FL_PLD + cb + i * 4] = src[i];
    }
    __syncwarp();

    // hoist Q fragments to registers (jt-invariant)
    unsigned qa[8][4];
#pragma unroll
    for (int kk = 0; kk < 8; kk++) {
        qa[kk][0] = Ps[(rb + g)     * FL_PLD + kk * 8 + t];
        qa[kk][1] = Ps[(rb + g + 8) * FL_PLD + kk * 8 + t];
        qa[kk][2] = Ps[(rb + g)     * FL_PLD + kk * 8 + t + 4];
        qa[kk][3] = Ps[(rb + g + 8) * FL_PLD + kk * 8 + t + 4];
    }
    __syncwarp();   // Ps region now free for P (warp-private)

    float o[8][4];
#pragma unroll
    for (int ni = 0; ni < 8; ni++)
#pragma unroll
        for (int e = 0; e < 4; e++) o[ni][e] = 0.f;
    float m0 = -1e30f, m1 = -1e30f, l0 = 0.f, l1 = 0.f;

    for (int jt = 0; jt <= qt; jt++) {
        // stage K and V tiles (pure bit copies)
        {
            const int r = tid >> 1, cb = (tid & 1) * 32;
            const uint4* ks = (const uint4*)&g_k[(size_t)(jt * 64 + r) * DIM + hoff + cb];
            const uint4* vs = (const uint4*)&g_v[(size_t)(jt * 64 + r) * DIM + hoff + cb];
#pragma unroll
            for (int i = 0; i < 8; i++) {
                *(uint4*)&Ks[r * FL_KLD + cb + i * 4] = ks[i];
                *(uint4*)&Vs[r * FL_VLD + cb + i * 4] = vs[i];
            }
        }
        __syncthreads();

        // S = Q @ K^T
        float s[8][4];
#pragma unroll
        for (int ni = 0; ni < 8; ni++)
#pragma unroll
            for (int e = 0; e < 4; e++) s[ni][e] = 0.f;

#pragma unroll
        for (int kk = 0; kk < 8; kk++) {
#pragma unroll
            for (int ni = 0; ni < 8; ni++) {
                const unsigned b0 = Ks[(ni * 8 + g) * FL_KLD + kk * 8 + t];
                const unsigned b1 = Ks[(ni * 8 + g) * FL_KLD + kk * 8 + t + 4];
                mma_tf32(s[ni], qa[kk][0], qa[kk][1], qa[kk][2], qa[kk][3], b0, b1);
            }
        }

        // causal mask (diagonal tile only)
        if (jt == qt) {
            const int li0 = rb + g, li1 = li0 + 8;
#pragma unroll
            for (int ni = 0; ni < 8; ni++) {
                const int j0 = ni * 8 + 2 * t, j1 = j0 + 1;
                if (j0 > li0) s[ni][0] = -1e30f;
                if (j1 > li0) s[ni][1] = -1e30f;
                if (j0 > li1) s[ni][2] = -1e30f;
                if (j1 > li1) s[ni][3] = -1e30f;
            }
        }

        // online softmax
        float rm0 = -1e30f, rm1 = -1e30f;
#pragma unroll
        for (int ni = 0; ni < 8; ni++) {
            rm0 = fmaxf(rm0, fmaxf(s[ni][0], s[ni][1]));
            rm1 = fmaxf(rm1, fmaxf(s[ni][2], s[ni][3]));
        }
        rm0 = fmaxf(rm0, __shfl_xor_sync(0xffffffffu, rm0, 1));
        rm0 = fmaxf(rm0, __shfl_xor_sync(0xffffffffu, rm0, 2));
        rm1 = fmaxf(rm1, __shfl_xor_sync(0xffffffffu, rm1, 1));
        rm1 = fmaxf(rm1, __shfl_xor_sync(0xffffffffu, rm1, 2));

        const float mn0 = fmaxf(m0, rm0), mn1 = fmaxf(m1, rm1);
        const float corr0 = __expf(m0 - mn0), corr1 = __expf(m1 - mn1);
        m0 = mn0; m1 = mn1;

        float rs0 = 0.f, rs1 = 0.f;
#pragma unroll
        for (int ni = 0; ni < 8; ni++) {
            s[ni][0] = __expf(s[ni][0] - mn0);
            s[ni][1] = __expf(s[ni][1] - mn0);
            s[ni][2] = __expf(s[ni][2] - mn1);
            s[ni][3] = __expf(s[ni][3] - mn1);
            rs0 += s[ni][0] + s[ni][1];
            rs1 += s[ni][2] + s[ni][3];
            Ps[(rb + g)     * FL_PLD + ni * 8 + 2 * t]     = f2tf(s[ni][0]);
            Ps[(rb + g)     * FL_PLD + ni * 8 + 2 * t + 1] = f2tf(s[ni][1]);
            Ps[(rb + g + 8) * FL_PLD + ni * 8 + 2 * t]     = f2tf(s[ni][2]);
            Ps[(rb + g + 8) * FL_PLD + ni * 8 + 2 * t + 1] = f2tf(s[ni][3]);
        }
        rs0 += __shfl_xor_sync(0xffffffffu, rs0, 1);
        rs0 += __shfl_xor_sync(0xffffffffu, rs0, 2);
        rs1 += __shfl_xor_sync(0xffffffffu, rs1, 1);
        rs1 += __shfl_xor_sync(0xffffffffu, rs1, 2);
        l0 = l0 * corr0 + rs0;
        l1 = l1 * corr1 + rs1;

#pragma unroll
        for (int ni = 0; ni < 8; ni++) {
            o[ni][0] *= corr0; o[ni][1] *= corr0;
            o[ni][2] *= corr1; o[ni][3] *= corr1;
        }
        __syncwarp();   // Ps write -> read is warp-local

        // O += P @ V
#pragma unroll
        for (int kk = 0; kk < 8; kk++) {
            const unsigned a0 = Ps[(rb + g)     * FL_PLD + kk * 8 + t];
            const unsigned a1 = Ps[(rb + g + 8) * FL_PLD + kk * 8 + t];
            const unsigned a2 = Ps[(rb + g)     * FL_PLD + kk * 8 + t + 4];
            const unsigned a3 = Ps[(rb + g + 8) * FL_PLD + kk * 8 + t + 4];
#pragma unroll
            for (int ni = 0; ni < 8; ni++) {
                const unsigned b0 = Vs[(kk * 8 + t)     * FL_VLD + ni * 8 + g];
                const unsigned b1 = Vs[(kk * 8 + t + 4) * FL_VLD + ni * 8 + g];
                mma_tf32(o[ni], a0, a1, a2, a3, b0, b1);
            }
        }
        __syncthreads();   // protect K/V tiles before next stage
    }

    // normalize + write tf32 bits (out_kernel consumes bits directly)
    const float inv0 = 1.f / l0, inv1 = 1.f / l1;
    const int row = qt * 64 + rb;
#pragma unroll
    for (int ni = 0; ni < 8; ni++) {
        const int cb = hoff + ni * 8 + 2 * t;
        uint2 v0 = { f2tf(o[ni][0] * inv0), f2tf(o[ni][1] * inv0) };
        uint2 v1 = { f2tf(o[ni][2] * inv1), f2tf(o[ni][3] * inv1) };
        *(uint2*)&g_att[(size_t)(row + g)     * DIM + cb] = v0;
        *(uint2*)&g_att[(size_t)(row + g + 8) * DIM + cb] = v1;
    }
}

// ---------------------------------------------------------------------------
extern "C" void kernel_launch(void* const* d_in, const int* in_sizes, int n_in,
                              void* d_out, int out_size)
{
    const float* x  = (const float*)d_in[0];
    const float* Wq = (const float*)d_in[1];
    const float* Wk = (const float*)d_in[2];
    const float* Wv = (const float*)d_in[3];
    const float* Wo = (const float*)d_in[4];
    const float* bo = (const float*)d_in[5];
    float* out = (float*)d_out;

    cudaFuncSetAttribute(flash_kernel,
                         cudaFuncAttributeMaxDynamicSharedMemorySize,
                         FL_SMEM_BYTES);

    qkv_kernel<<<dim3(DIM / 64, SEQ / 128, 3), 256>>>(x, Wq, Wk, Wv);
    flash_kernel<<<dim3(SEQ / 64, HEADS), 128, FL_SMEM_BYTES>>>();
    out_kernel<<<dim3(DIM / 64, SEQ / 128), 256>>>(Wo, bo, out);
}

// round 8
// speedup vs baseline: 2.2488x; 1.5964x over previous
#include <cuda_runtime.h>
#include <cstdint>

#define SEQ    4096
#define DIM    1024
#define HEADS  16
#define DHEAD  64
#define QBETA  0.125f   // 1/sqrt(64)

// Scratch (allocation-free rule: __device__ globals).
// Q/K/V/att hold tf32 BIT PATTERNS — rounding just happens earlier; numerics identical.
__device__ unsigned g_q[SEQ * DIM];
__device__ unsigned g_k[SEQ * DIM];
__device__ unsigned g_v[SEQ * DIM];
__device__ unsigned g_att[SEQ * DIM];

// ---------------------------------------------------------------------------
// tf32 helpers
// ---------------------------------------------------------------------------
__device__ __forceinline__ unsigned f2tf(float x) {
    unsigned u;
    asm("cvt.rna.tf32.f32 %0, %1;" : "=r"(u) : "f"(x));
    return u;
}

__device__ __forceinline__ void mma_tf32(float* c,
                                         unsigned a0, unsigned a1, unsigned a2, unsigned a3,
                                         unsigned b0, unsigned b1) {
    asm volatile(
        "mma.sync.aligned.m16n8k8.row.col.f32.tf32.tf32.f32 "
        "{%0,%1,%2,%3},{%4,%5,%6,%7},{%8,%9},{%0,%1,%2,%3};"
        : "+f"(c[0]), "+f"(c[1]), "+f"(c[2]), "+f"(c[3])
        : "r"(a0), "r"(a1), "r"(a2), "r"(a3), "r"(b0), "r"(b1));
}

__device__ __forceinline__ unsigned smem_u32(const void* p) {
    return (unsigned)__cvta_generic_to_shared(p);
}
__device__ __forceinline__ void cp16(unsigned dst, const void* src) {
    asm volatile("cp.async.cg.shared.global [%0], [%1], 16;" :: "r"(dst), "l"(src));
}

// ---------------------------------------------------------------------------
// tf32 GEMM (R3-proven shape): block tile 128x64, K-step 32, 256 threads =
// 8 warps (4x2), warp tile 32x32. A ld=36, B ld=72, conflict-free gathers.
// ---------------------------------------------------------------------------
#define GA_LD 36
#define GB_LD 72

template<bool A_TF32, bool OUT_TF32>
__device__ __forceinline__ void gemm_tile(
    const void* __restrict__ Ap, const float* __restrict__ B,
    void* __restrict__ Cp, float alpha, const float* __restrict__ bias)
{
    __shared__ unsigned As[128 * GA_LD];
    __shared__ unsigned Bs[32 * GB_LD];

    const int tid  = threadIdx.x;
    const int lane = tid & 31;
    const int warp = tid >> 5;
    const int g = lane >> 2;
    const int t = lane & 3;
    const int wm = warp & 3;
    const int wn = warp >> 2;
    const int row0 = blockIdx.y * 128;
    const int col0 = blockIdx.x * 64;

    float acc[2][4][4];
#pragma unroll
    for (int mi = 0; mi < 2; mi++)
#pragma unroll
        for (int ni = 0; ni < 4; ni++)
#pragma unroll
            for (int e = 0; e < 4; e++) acc[mi][ni][e] = 0.f;

    for (int k0 = 0; k0 < DIM; k0 += 32) {
#pragma unroll
        for (int p = 0; p < 4; p++) {
            const int r = (tid >> 3) + p * 32;
            const int c = (tid & 7) * 4;
            if (A_TF32) {
                const unsigned* A32 = (const unsigned*)Ap;
                *(uint4*)&As[r * GA_LD + c] =
                    *(const uint4*)&A32[(size_t)(row0 + r) * DIM + k0 + c];
            } else {
                const float* Af = (const float*)Ap;
                float4 v = *(const float4*)&Af[(size_t)(row0 + r) * DIM + k0 + c];
                unsigned* d = &As[r * GA_LD + c];
                d[0] = f2tf(v.x); d[1] = f2tf(v.y); d[2] = f2tf(v.z); d[3] = f2tf(v.w);
            }
        }
#pragma unroll
        for (int p = 0; p < 2; p++) {
            const int r = (tid >> 4) + p * 16;
            const int c = (tid & 15) * 4;
            float4 v = *(const float4*)&B[(size_t)(k0 + r) * DIM + col0 + c];
            unsigned* d = &Bs[r * GB_LD + c];
            d[0] = f2tf(v.x); d[1] = f2tf(v.y); d[2] = f2tf(v.z); d[3] = f2tf(v.w);
        }
        __syncthreads();

#pragma unroll
        for (int kk = 0; kk < 4; kk++) {
            unsigned a[2][4];
#pragma unroll
            for (int mi = 0; mi < 2; mi++) {
                const int rbm = wm * 32 + mi * 16;
                a[mi][0] = As[(rbm + g)     * GA_LD + kk * 8 + t];
                a[mi][1] = As[(rbm + g + 8) * GA_LD + kk * 8 + t];
                a[mi][2] = As[(rbm + g)     * GA_LD + kk * 8 + t + 4];
                a[mi][3] = As[(rbm + g + 8) * GA_LD + kk * 8 + t + 4];
            }
#pragma unroll
            for (int ni = 0; ni < 4; ni++) {
                const unsigned b0 = Bs[(kk * 8 + t)     * GB_LD + wn * 32 + ni * 8 + g];
                const unsigned b1 = Bs[(kk * 8 + t + 4) * GB_LD + wn * 32 + ni * 8 + g];
                mma_tf32(acc[0][ni], a[0][0], a[0][1], a[0][2], a[0][3], b0, b1);
                mma_tf32(acc[1][ni], a[1][0], a[1][1], a[1][2], a[1][3], b0, b1);
            }
        }
        __syncthreads();
    }

#pragma unroll
    for (int mi = 0; mi < 2; mi++) {
        const int rb = row0 + wm * 32 + mi * 16;
#pragma unroll
        for (int ni = 0; ni < 4; ni++) {
            const int cb = col0 + wn * 32 + ni * 8 + 2 * t;
            float bv0 = 0.f, bv1 = 0.f;
            if (bias) { bv0 = bias[cb]; bv1 = bias[cb + 1]; }
            float v00 = acc[mi][ni][0] * alpha + bv0;
            float v01 = acc[mi][ni][1] * alpha + bv1;
            float v10 = acc[mi][ni][2] * alpha + bv0;
            float v11 = acc[mi][ni][3] * alpha + bv1;
            if (OUT_TF32) {
                unsigned* C32 = (unsigned*)Cp;
                uint2 o0 = { f2tf(v00), f2tf(v01) };
                uint2 o1 = { f2tf(v10), f2tf(v11) };
                *(uint2*)&C32[(size_t)(rb + g)     * DIM + cb] = o0;
                *(uint2*)&C32[(size_t)(rb + g + 8) * DIM + cb] = o1;
            } else {
                float* Cf = (float*)Cp;
                float2 o0 = { v00, v01 };
                float2 o1 = { v10, v11 };
                *(float2*)&Cf[(size_t)(rb + g)     * DIM + cb] = o0;
                *(float2*)&Cf[(size_t)(rb + g + 8) * DIM + cb] = o1;
            }
        }
    }
}

__global__ void __launch_bounds__(256) qkv_kernel(
    const float* __restrict__ x,
    const float* __restrict__ Wq,
    const float* __restrict__ Wk,
    const float* __restrict__ Wv)
{
    if (blockIdx.z == 0)      gemm_tile<false, true>(x, Wq, g_q, QBETA, nullptr);
    else if (blockIdx.z == 1) gemm_tile<false, true>(x, Wk, g_k, 1.f, nullptr);
    else                      gemm_tile<false, true>(x, Wv, g_v, 1.f, nullptr);
}

__global__ void __launch_bounds__(256) out_kernel(
    const float* __restrict__ Wo,
    const float* __restrict__ bo,
    float* __restrict__ out)
{
    gemm_tile<true, false>(g_att, Wo, out, 1.f, bo);
}

// ---------------------------------------------------------------------------
// Flash attention v2: Br=128 (256 threads, 8 warps, 16 q-rows/warp),
// Bc=64, K/V double-buffered via cp.async.
// smem: 2 stages x (K[64][68] + V[64][72]) + P[128][68] = 104KB -> 2 blocks/SM.
// ---------------------------------------------------------------------------
#define FL_KLD 68
#define FL_VLD 72
#define FL_PLD 68
#define FL_STAGE_UINTS (64 * FL_KLD + 64 * FL_VLD)        // 8960
#define OFF_KV(b) ((b) * FL_STAGE_UINTS)
#define OFF_P (2 * FL_STAGE_UINTS)
#define FL_SMEM_UINTS (OFF_P + 128 * FL_PLD)
#define FL_SMEM_BYTES (FL_SMEM_UINTS * 4)                 // 106496 B

__device__ __forceinline__ void stage_kv(unsigned* buf, int jt, int hoff, int tid)
{
    unsigned* Ks = buf;
    unsigned* Vs = buf + 64 * FL_KLD;
#pragma unroll
    for (int p = 0; p < 4; p++) {
        const int idx = tid + p * 256;
        const int r  = idx >> 4;
        const int c4 = (idx & 15) * 4;
        cp16(smem_u32(&Ks[r * FL_KLD + c4]),
             &g_k[(size_t)(jt * 64 + r) * DIM + hoff + c4]);
        cp16(smem_u32(&Vs[r * FL_VLD + c4]),
             &g_v[(size_t)(jt * 64 + r) * DIM + hoff + c4]);
    }
    asm volatile("cp.async.commit_group;");
}

__global__ void __launch_bounds__(256, 2) flash_kernel()
{
    extern __shared__ unsigned sm[];
    unsigned* Ps = sm + OFF_P;

    const int tid  = threadIdx.x;
    const int lane = tid & 31;
    const int warp = tid >> 5;
    const int g = lane >> 2;
    const int t = lane & 3;
    const int h   = blockIdx.y;
    const int qt2 = gridDim.x - 1 - blockIdx.x;   // heaviest q-tiles first
    const int hoff = h * DHEAD;
    const int rb = warp * 16;                     // warp's local row base (0..112)
    const int jtmax = 2 * qt2 + 1;

    // kick off stage 0 immediately
    stage_kv(sm + OFF_KV(0), 0, hoff, tid);

    // stage Q (bits) into P region, then hoist fragments (overlaps cp.async)
    {
        const int r = tid >> 1, cb = (tid & 1) * 32;
        const uint4* src = (const uint4*)&g_q[(size_t)(qt2 * 128 + r) * DIM + hoff + cb];
#pragma unroll
        for (int i = 0; i < 8; i++)
            *(uint4*)&Ps[r * FL_PLD + cb + i * 4] = src[i];
    }
    __syncwarp();
    unsigned qa[8][4];
#pragma unroll
    for (int kk = 0; kk < 8; kk++) {
        qa[kk][0] = Ps[(rb + g)     * FL_PLD + kk * 8 + t];
        qa[kk][1] = Ps[(rb + g + 8) * FL_PLD + kk * 8 + t];
        qa[kk][2] = Ps[(rb + g)     * FL_PLD + kk * 8 + t + 4];
        qa[kk][3] = Ps[(rb + g + 8) * FL_PLD + kk * 8 + t + 4];
    }
    __syncwarp();   // Ps region now free for P (warp-private rows)

    float o[8][4];
#pragma unroll
    for (int ni = 0; ni < 8; ni++)
#pragma unroll
        for (int e = 0; e < 4; e++) o[ni][e] = 0.f;
    float m0 = -1e30f, m1 = -1e30f, l0 = 0.f, l1 = 0.f;

    for (int jt = 0; jt <= jtmax; jt++) {
        const int cur = jt & 1;
        unsigned* Ks = sm + OFF_KV(cur);
        unsigned* Vs = Ks + 64 * FL_KLD;

        if (jt < jtmax) {
            stage_kv(sm + OFF_KV(cur ^ 1), jt + 1, hoff, tid);
            asm volatile("cp.async.wait_group 1;");
        } else {
            asm volatile("cp.async.wait_group 0;");
        }
        __syncthreads();

        // skip fully-masked diagonal half-tiles (uniform per warp, between barriers)
        const bool active = (jt * 64 <= qt2 * 128 + rb + 15);
        if (active) {
            // S = Q @ K^T
            float s[8][4];
#pragma unroll
            for (int ni = 0; ni < 8; ni++)
#pragma unroll
                for (int e = 0; e < 4; e++) s[ni][e] = 0.f;

#pragma unroll
            for (int kk = 0; kk < 8; kk++) {
#pragma unroll
                for (int ni = 0; ni < 8; ni++) {
                    const unsigned b0 = Ks[(ni * 8 + g) * FL_KLD + kk * 8 + t];
                    const unsigned b1 = Ks[(ni * 8 + g) * FL_KLD + kk * 8 + t + 4];
                    mma_tf32(s[ni], qa[kk][0], qa[kk][1], qa[kk][2], qa[kk][3], b0, b1);
                }
            }

            // causal mask — only tiles that can straddle the diagonal
            if (jt >= 2 * qt2) {
                const int gr0 = qt2 * 128 + rb + g;
                const int gr1 = gr0 + 8;
                const int cb0 = jt * 64;
#pragma unroll
                for (int ni = 0; ni < 8; ni++) {
                    const int j0 = cb0 + ni * 8 + 2 * t, j1 = j0 + 1;
                    if (j0 > gr0) s[ni][0] = -1e30f;
                    if (j1 > gr0) s[ni][1] = -1e30f;
                    if (j0 > gr1) s[ni][2] = -1e30f;
                    if (j1 > gr1) s[ni][3] = -1e30f;
                }
            }

            // online softmax
            float rm0 = -1e30f, rm1 = -1e30f;
#pragma unroll
            for (int ni = 0; ni < 8; ni++) {
                rm0 = fmaxf(rm0, fmaxf(s[ni][0], s[ni][1]));
                rm1 = fmaxf(rm1, fmaxf(s[ni][2], s[ni][3]));
            }
            rm0 = fmaxf(rm0, __shfl_xor_sync(0xffffffffu, rm0, 1));
            rm0 = fmaxf(rm0, __shfl_xor_sync(0xffffffffu, rm0, 2));
            rm1 = fmaxf(rm1, __shfl_xor_sync(0xffffffffu, rm1, 1));
            rm1 = fmaxf(rm1, __shfl_xor_sync(0xffffffffu, rm1, 2));

            const float mn0 = fmaxf(m0, rm0), mn1 = fmaxf(m1, rm1);
            const float corr0 = __expf(m0 - mn0), corr1 = __expf(m1 - mn1);
            m0 = mn0; m1 = mn1;

            float rs0 = 0.f, rs1 = 0.f;
#pragma unroll
            for (int ni = 0; ni < 8; ni++) {
                s[ni][0] = __expf(s[ni][0] - mn0);
                s[ni][1] = __expf(s[ni][1] - mn0);
                s[ni][2] = __expf(s[ni][2] - mn1);
                s[ni][3] = __expf(s[ni][3] - mn1);
                rs0 += s[ni][0] + s[ni][1];
                rs1 += s[ni][2] + s[ni][3];
                Ps[(rb + g)     * FL_PLD + ni * 8 + 2 * t]     = f2tf(s[ni][0]);
                Ps[(rb + g)     * FL_PLD + ni * 8 + 2 * t + 1] = f2tf(s[ni][1]);
                Ps[(rb + g + 8) * FL_PLD + ni * 8 + 2 * t]     = f2tf(s[ni][2]);
                Ps[(rb + g + 8) * FL_PLD + ni * 8 + 2 * t + 1] = f2tf(s[ni][3]);
            }
            rs0 += __shfl_xor_sync(0xffffffffu, rs0, 1);
            rs0 += __shfl_xor_sync(0xffffffffu, rs0, 2);
            rs1 += __shfl_xor_sync(0xffffffffu, rs1, 1);
            rs1 += __shfl_xor_sync(0xffffffffu, rs1, 2);
            l0 = l0 * corr0 + rs0;
            l1 = l1 * corr1 + rs1;

#pragma unroll
            for (int ni = 0; ni < 8; ni++) {
                o[ni][0] *= corr0; o[ni][1] *= corr0;
                o[ni][2] *= corr1; o[ni][3] *= corr1;
            }
            __syncwarp();

            // O += P @ V
#pragma unroll
            for (int kk = 0; kk < 8; kk++) {
                const unsigned a0 = Ps[(rb + g)     * FL_PLD + kk * 8 + t];
                const unsigned a1 = Ps[(rb + g + 8) * FL_PLD + kk * 8 + t];
                const unsigned a2 = Ps[(rb + g)     * FL_PLD + kk * 8 + t + 4];
                const unsigned a3 = Ps[(rb + g + 8) * FL_PLD + kk * 8 + t + 4];
#pragma unroll
                for (int ni = 0; ni < 8; ni++) {
                    const unsigned b0 = Vs[(kk * 8 + t)     * FL_VLD + ni * 8 + g];
                    const unsigned b1 = Vs[(kk * 8 + t + 4) * FL_VLD + ni * 8 + g];
                    mma_tf32(o[ni], a0, a1, a2, a3, b0, b1);
                }
            }
        }
        __syncthreads();   // protect K/V buffer before it is restaged
    }

    // normalize + write tf32 bits
    const float inv0 = 1.f / l0, inv1 = 1.f / l1;
    const int row = qt2 * 128 + rb;
#pragma unroll
    for (int ni = 0; ni < 8; ni++) {
        const int cb = hoff + ni * 8 + 2 * t;
        uint2 v0 = { f2tf(o[ni][0] * inv0), f2tf(o[ni][1] * inv0) };
        uint2 v1 = { f2tf(o[ni][2] * inv1), f2tf(o[ni][3] * inv1) };
        *(uint2*)&g_att[(size_t)(row + g)     * DIM + cb] = v0;
        *(uint2*)&g_att[(size_t)(row + g + 8) * DIM + cb] = v1;
    }
}

// ---------------------------------------------------------------------------
extern "C" void kernel_launch(void* const* d_in, const int* in_sizes, int n_in,
                              void* d_out, int out_size)
{
    const float* x  = (const float*)d_in[0];
    const float* Wq = (const float*)d_in[1];
    const float* Wk = (const float*)d_in[2];
    const float* Wv = (const float*)d_in[3];
    const float* Wo = (const float*)d_in[4];
    const float* bo = (const float*)d_in[5];
    float* out = (float*)d_out;

    cudaFuncSetAttribute(flash_kernel,
                         cudaFuncAttributeMaxDynamicSharedMemorySize,
                         FL_SMEM_BYTES);

    qkv_kernel<<<dim3(DIM / 64, SEQ / 128, 3), 256>>>(x, Wq, Wk, Wv);
    flash_kernel<<<dim3(SEQ / 128, HEADS), 256, FL_SMEM_BYTES>>>();
    out_kernel<<<dim3(DIM / 64, SEQ / 128), 256>>>(Wo, bo, out);
}